// round 1
// baseline (speedup 1.0000x reference)
#include <cuda_runtime.h>
#include <math.h>
#include <stdint.h>

#define NB   1024
#define NS   500
#define RR   128
#define LATC 12
#define FEATC 64
#define HIDC 128
#define CINC 21            // 9 raw inputs + 12 folded latent channels
#define GC   13            // grid channels: 1 sdf + 12 latent

// ---------------- scratch (static device arrays; no runtime alloc) ----------
__device__ float g_sdf[NB * NS];
__device__ float g_rgbp[NB * NS * 3];
__device__ float g_cw[CINC * HIDC];   // combined first-layer weights
__device__ float g_cb[HIDC];          // combined first-layer bias
__device__ float g_w2t[3 * HIDC];     // W2 transposed [c][j]
__device__ float g_b2c[3];

// ---------------- prep: fold feature layer into W1 --------------------------
__global__ void prep_kernel(const float* __restrict__ Wf, const float* __restrict__ bf,
                            const float* __restrict__ W1, const float* __restrict__ b1,
                            const float* __restrict__ W2, const float* __restrict__ b2) {
    int j = threadIdx.x;
    if (j >= HIDC) return;
    // rows 0..8 copied straight from W1 (pts, grads, viewdirs)
    for (int k = 0; k < 9; k++) g_cw[k * HIDC + j] = W1[k * HIDC + j];
    // b_eff = b1 + b_feat @ W1[9:]
    double acc = (double)b1[j];
    for (int c = 0; c < FEATC; c++)
        acc += (double)bf[c] * (double)W1[(9 + c) * HIDC + j];
    g_cb[j] = (float)acc;
    // W_eff[l] = W_feat[l] @ W1[9:]
    for (int l = 0; l < LATC; l++) {
        double a = 0.0;
        for (int c = 0; c < FEATC; c++)
            a += (double)Wf[l * FEATC + c] * (double)W1[(9 + c) * HIDC + j];
        g_cw[(9 + l) * HIDC + j] = (float)a;
    }
    for (int c = 0; c < 3; c++) g_w2t[c * HIDC + j] = W2[j * 3 + c];
    if (j < 3) g_b2c[j] = b2[j];
}

// ---------------- per-point: trilerp + grad + MLP ---------------------------
__global__ void __launch_bounds__(256)
point_kernel(const float* __restrict__ ro, const float* __restrict__ rd,
             const float* __restrict__ vdir, const float* __restrict__ grid) {
    __shared__ float sW[CINC * HIDC];
    __shared__ float sB[HIDC];
    __shared__ float sW2[3 * HIDC];
    __shared__ float sB2[4];
    for (int i = threadIdx.x; i < CINC * HIDC; i += blockDim.x) sW[i] = g_cw[i];
    for (int i = threadIdx.x; i < HIDC; i += blockDim.x) sB[i] = g_cb[i];
    for (int i = threadIdx.x; i < 3 * HIDC; i += blockDim.x) sW2[i] = g_w2t[i];
    if (threadIdx.x < 3) sB2[threadIdx.x] = g_b2c[threadIdx.x];
    __syncthreads();

    int idx = blockIdx.x * blockDim.x + threadIdx.x;
    if (idx >= NB * NS) return;
    int ray = idx / NS;
    int s   = idx - ray * NS;

    // z and pt with explicit non-fused ops to bit-match XLA's mul+add (mask decision)
    float lin = __fmul_rn((float)s, 1.0f / 499.0f);
    float z   = __fadd_rn(0.5f, __fmul_rn(3.0f, lin));
    float ox = ro[ray * 3 + 0], oy = ro[ray * 3 + 1], oz = ro[ray * 3 + 2];
    float dx = rd[ray * 3 + 0], dy = rd[ray * 3 + 1], dz = rd[ray * 3 + 2];
    float px = __fadd_rn(ox, __fmul_rn(dx, z));
    float py = __fadd_rn(oy, __fmul_rn(dy, z));
    float pz = __fadd_rn(oz, __fmul_rn(dz, z));

    bool outb = (px < -1.0f) | (px > 1.0f) | (py < -1.0f) | (py > 1.0f) |
                (pz < -1.0f) | (pz > 1.0f);
    if (outb) {
        g_sdf[idx] = 100.0f;
        g_rgbp[idx * 3 + 0] = 0.0f;
        g_rgbp[idx * 3 + 1] = 0.0f;
        g_rgbp[idx * 3 + 2] = 0.0f;
        return;
    }

    // ---- trilinear interp of 13 channels + analytic grad of channel 0 ----
    float ux = fminf(fmaxf((px + 1.0f) * 0.5f * 127.0f, 0.0f), 127.0f);
    float uy = fminf(fmaxf((py + 1.0f) * 0.5f * 127.0f, 0.0f), 127.0f);
    float uz = fminf(fmaxf((pz + 1.0f) * 0.5f * 127.0f, 0.0f), 127.0f);
    int ix = min((int)ux, RR - 2);
    int iy = min((int)uy, RR - 2);
    int iz = min((int)uz, RR - 2);
    float fx = ux - (float)ix, fy = uy - (float)iy, fz = uz - (float)iz;
    float wx[2] = {1.0f - fx, fx};
    float wy[2] = {1.0f - fy, fy};
    float wz[2] = {1.0f - fz, fz};

    const float* gp = grid + ((size_t)((ix * RR + iy) * RR + iz)) * GC;
    float vv[GC];
#pragma unroll
    for (int c = 0; c < GC; c++) vv[c] = 0.0f;
    float gxa = 0.0f, gya = 0.0f, gza = 0.0f;

#pragma unroll
    for (int cx = 0; cx < 2; cx++) {
#pragma unroll
        for (int cy = 0; cy < 2; cy++) {
#pragma unroll
            for (int cz = 0; cz < 2; cz++) {
                const float* cp = gp + cx * (RR * RR * GC) + cy * (RR * GC) + cz * GC;
                float wyz = wy[cy] * wz[cz];
                float wxz = wx[cx] * wz[cz];
                float wxy = wx[cx] * wy[cy];
                float w   = wx[cx] * wyz;
                float c0  = cp[0];
                vv[0] = fmaf(w, c0, vv[0]);
                gxa = fmaf(cx ? wyz : -wyz, c0, gxa);
                gya = fmaf(cy ? wxz : -wxz, c0, gya);
                gza = fmaf(cz ? wxy : -wxy, c0, gza);
#pragma unroll
                for (int c = 1; c < GC; c++) vv[c] = fmaf(w, cp[c], vv[c]);
            }
        }
    }

    // ---- assemble inputs: [pt, grad, viewdir, lat(folded)] ----
    float hh[CINC];
    hh[0] = px; hh[1] = py; hh[2] = pz;
    hh[3] = gxa * 63.5f; hh[4] = gya * 63.5f; hh[5] = gza * 63.5f;
    hh[6] = vdir[ray * 3 + 0]; hh[7] = vdir[ray * 3 + 1]; hh[8] = vdir[ray * 3 + 2];
#pragma unroll
    for (int l = 0; l < LATC; l++) hh[9 + l] = vv[1 + l];

    // ---- MLP: hidden = relu(h @ CW + cb); rgb = sigmoid(hidden @ W2 + b2) ----
    const float4* sW4  = (const float4*)sW;
    const float4* sB4  = (const float4*)sB;
    const float4* sW24 = (const float4*)sW2;
    float r0 = 0.0f, r1 = 0.0f, r2 = 0.0f;
    for (int jq = 0; jq < HIDC / 4; jq++) {
        float4 a = sB4[jq];
#pragma unroll
        for (int k = 0; k < CINC; k++) {
            float4 wv = sW4[k * (HIDC / 4) + jq];
            a.x = fmaf(hh[k], wv.x, a.x);
            a.y = fmaf(hh[k], wv.y, a.y);
            a.z = fmaf(hh[k], wv.z, a.z);
            a.w = fmaf(hh[k], wv.w, a.w);
        }
        a.x = fmaxf(a.x, 0.0f);
        a.y = fmaxf(a.y, 0.0f);
        a.z = fmaxf(a.z, 0.0f);
        a.w = fmaxf(a.w, 0.0f);
        float4 w0 = sW24[0 * (HIDC / 4) + jq];
        float4 w1 = sW24[1 * (HIDC / 4) + jq];
        float4 w2 = sW24[2 * (HIDC / 4) + jq];
        r0 = fmaf(a.x, w0.x, fmaf(a.y, w0.y, fmaf(a.z, w0.z, fmaf(a.w, w0.w, r0))));
        r1 = fmaf(a.x, w1.x, fmaf(a.y, w1.y, fmaf(a.z, w1.z, fmaf(a.w, w1.w, r1))));
        r2 = fmaf(a.x, w2.x, fmaf(a.y, w2.y, fmaf(a.z, w2.z, fmaf(a.w, w2.w, r2))));
    }
    g_sdf[idx] = vv[0];
    g_rgbp[idx * 3 + 0] = 1.0f / (1.0f + expf(-(r0 + sB2[0])));
    g_rgbp[idx * 3 + 1] = 1.0f / (1.0f + expf(-(r1 + sB2[1])));
    g_rgbp[idx * 3 + 2] = 1.0f / (1.0f + expf(-(r2 + sB2[2])));
}

// ---------------- per-ray: transmittance scan + accumulation ----------------
__global__ void __launch_bounds__(256)
integrate_kernel(const float* __restrict__ rd, const float* __restrict__ beta_p,
                 float* __restrict__ out) {
    int gwarp = (blockIdx.x * blockDim.x + threadIdx.x) >> 5;
    int lane  = threadIdx.x & 31;
    if (gwarp >= NB) return;
    const unsigned FULL = 0xffffffffu;

    float beff = fabsf(beta_p[0]) + 1e-4f;
    float rb   = 1.0f / beff;
    float dx = rd[gwarp * 3 + 0], dy = rd[gwarp * 3 + 1], dz = rd[gwarp * 3 + 2];
    float dn = sqrtf(dx * dx + dy * dy + dz * dz);

    float carry = 0.0f, aR = 0.0f, aG = 0.0f, aB = 0.0f, aD = 0.0f;

    for (int chunk = 0; chunk < (NS + 31) / 32; chunk++) {
        int s = chunk * 32 + lane;
        bool in = s < NS;
        float sdf = in ? g_sdf[gwarp * NS + s] : 100.0f;

        float lin = __fmul_rn((float)s, 1.0f / 499.0f);
        float z   = __fadd_rn(0.5f, __fmul_rn(3.0f, lin));
        int sd = (s >= NS - 1) ? NS - 2 : s;
        float l0 = __fmul_rn((float)sd, 1.0f / 499.0f);
        float l1 = __fmul_rn((float)(sd + 1), 1.0f / 499.0f);
        float z0 = __fadd_rn(0.5f, __fmul_rn(3.0f, l0));
        float z1 = __fadd_rn(0.5f, __fmul_rn(3.0f, l1));
        float dist = z1 - z0;

        float asdf = fabsf(sdf);
        float sgn  = (sdf > 0.0f) ? 1.0f : ((sdf < 0.0f) ? -1.0f : 0.0f);
        float density = rb * (0.5f + 0.5f * sgn * expm1f(-asdf / beff));
        float fe = in ? dist * density : 0.0f;

        // inclusive warp scan of fe
        float sc = fe;
#pragma unroll
        for (int o = 1; o < 32; o <<= 1) {
            float t = __shfl_up_sync(FULL, sc, o);
            if (lane >= o) sc += t;
        }
        float T     = expf(-(carry + (sc - fe)));   // exclusive prefix
        float alpha = 1.0f - expf(-fe);
        float w     = in ? alpha * T : 0.0f;

        if (in) {
            int bidx = (gwarp * NS + s) * 3;
            aR = fmaf(w, g_rgbp[bidx + 0], aR);
            aG = fmaf(w, g_rgbp[bidx + 1], aG);
            aB = fmaf(w, g_rgbp[bidx + 2], aB);
            aD = fmaf(w, z * dn, aD);
        }
        carry += __shfl_sync(FULL, sc, 31);
    }

#pragma unroll
    for (int o = 16; o > 0; o >>= 1) {
        aR += __shfl_down_sync(FULL, aR, o);
        aG += __shfl_down_sync(FULL, aG, o);
        aB += __shfl_down_sync(FULL, aB, o);
        aD += __shfl_down_sync(FULL, aD, o);
    }
    if (lane == 0) {
        out[gwarp * 3 + 0] = aR;
        out[gwarp * 3 + 1] = aG;
        out[gwarp * 3 + 2] = aB;
        out[3 * NB + gwarp] = aD;
    }
}

// ---------------- launch -----------------------------------------------------
extern "C" void kernel_launch(void* const* d_in, const int* in_sizes, int n_in,
                              void* d_out, int out_size) {
    const float* ro   = (const float*)d_in[0];
    const float* rd   = (const float*)d_in[1];
    const float* vd   = (const float*)d_in[2];
    const float* grid = (const float*)d_in[3];
    const float* Wf   = (const float*)d_in[4];
    const float* bf   = (const float*)d_in[5];
    const float* W1   = (const float*)d_in[6];
    const float* b1   = (const float*)d_in[7];
    const float* W2   = (const float*)d_in[8];
    const float* b2   = (const float*)d_in[9];
    const float* beta = (const float*)d_in[10];
    float* out = (float*)d_out;

    prep_kernel<<<1, 128>>>(Wf, bf, W1, b1, W2, b2);
    point_kernel<<<(NB * NS + 255) / 256, 256>>>(ro, rd, vd, grid);
    integrate_kernel<<<(NB * 32 + 255) / 256, 256>>>(rd, beta, out);
}

// round 2
// speedup vs baseline: 1.2777x; 1.2777x over previous
#include <cuda_runtime.h>
#include <math.h>
#include <stdint.h>

#define NB   1024
#define NS   500
#define RR   128
#define LATC 12
#define FEATC 64
#define HIDC 128
#define CINC 21            // 9 raw inputs + 12 folded latent channels
#define GC   13            // grid channels: 1 sdf + 12 latent

// ---------------- scratch (static device arrays; no runtime alloc) ----------
__device__ float g_sdf[NB * NS];
__device__ float g_rgbp[NB * NS * 3];
__device__ float g_cw[CINC * HIDC];   // combined first-layer weights
__device__ float g_cb[HIDC];          // combined first-layer bias
__device__ float g_w2t[3 * HIDC];     // W2 transposed [c][j]
__device__ float g_b2c[3];

// ---------------- prep: fold feature layer into W1 (parallel, fp32) ---------
// grid = 13 blocks x 128 threads.
// blocks 0..11: block l, thread j computes W_eff[l][j] = Wf[l,:] @ W1[9:,j]
// block 12: copies rows 0..8, folds bias, transposes W2.
__global__ void prep_kernel(const float* __restrict__ Wf, const float* __restrict__ bf,
                            const float* __restrict__ W1, const float* __restrict__ b1,
                            const float* __restrict__ W2, const float* __restrict__ b2) {
    int j = threadIdx.x;
    int l = blockIdx.x;
    if (l < LATC) {
        float a0 = 0.f, a1 = 0.f, a2 = 0.f, a3 = 0.f;
#pragma unroll
        for (int c = 0; c < FEATC; c += 4) {
            a0 = fmaf(Wf[l * FEATC + c + 0], W1[(9 + c + 0) * HIDC + j], a0);
            a1 = fmaf(Wf[l * FEATC + c + 1], W1[(9 + c + 1) * HIDC + j], a1);
            a2 = fmaf(Wf[l * FEATC + c + 2], W1[(9 + c + 2) * HIDC + j], a2);
            a3 = fmaf(Wf[l * FEATC + c + 3], W1[(9 + c + 3) * HIDC + j], a3);
        }
        g_cw[(9 + l) * HIDC + j] = (a0 + a1) + (a2 + a3);
    } else {
        // rows 0..8 copied straight from W1 (pts, grads, viewdirs)
#pragma unroll
        for (int k = 0; k < 9; k++) g_cw[k * HIDC + j] = W1[k * HIDC + j];
        // b_eff = b1 + b_feat @ W1[9:]
        float a0 = 0.f, a1 = 0.f, a2 = 0.f, a3 = 0.f;
#pragma unroll
        for (int c = 0; c < FEATC; c += 4) {
            a0 = fmaf(bf[c + 0], W1[(9 + c + 0) * HIDC + j], a0);
            a1 = fmaf(bf[c + 1], W1[(9 + c + 1) * HIDC + j], a1);
            a2 = fmaf(bf[c + 2], W1[(9 + c + 2) * HIDC + j], a2);
            a3 = fmaf(bf[c + 3], W1[(9 + c + 3) * HIDC + j], a3);
        }
        g_cb[j] = b1[j] + ((a0 + a1) + (a2 + a3));
#pragma unroll
        for (int c = 0; c < 3; c++) g_w2t[c * HIDC + j] = W2[j * 3 + c];
        if (j < 3) g_b2c[j] = b2[j];
    }
}

// ---------------- per-point: trilerp + grad + MLP ---------------------------
__global__ void __launch_bounds__(256)
point_kernel(const float* __restrict__ ro, const float* __restrict__ rd,
             const float* __restrict__ vdir, const float* __restrict__ grid) {
    __shared__ float sW[CINC * HIDC];
    __shared__ float sB[HIDC];
    __shared__ float sW2[3 * HIDC];
    __shared__ float sB2[4];

    // ---- compute position/mask BEFORE touching shared weights ----
    int idx = blockIdx.x * blockDim.x + threadIdx.x;   // NB*NS divisible by 256
    int ray = idx / NS;
    int s   = idx - ray * NS;

    // z and pt with explicit non-fused ops to bit-match XLA's mul+add (mask decision)
    float lin = __fmul_rn((float)s, 1.0f / 499.0f);
    float z   = __fadd_rn(0.5f, __fmul_rn(3.0f, lin));
    float ox = ro[ray * 3 + 0], oy = ro[ray * 3 + 1], oz = ro[ray * 3 + 2];
    float dx = rd[ray * 3 + 0], dy = rd[ray * 3 + 1], dz = rd[ray * 3 + 2];
    float px = __fadd_rn(ox, __fmul_rn(dx, z));
    float py = __fadd_rn(oy, __fmul_rn(dy, z));
    float pz = __fadd_rn(oz, __fmul_rn(dz, z));

    bool outb = (px < -1.0f) | (px > 1.0f) | (py < -1.0f) | (py > 1.0f) |
                (pz < -1.0f) | (pz > 1.0f);
    if (outb) {
        g_sdf[idx] = 100.0f;
        // NOTE: rgb scratch intentionally NOT written: with sdf=100 the
        // integrate weight is exactly 0 (expm1(-1e6) == -1), so stale finite
        // rgb values contribute exactly 0. Deterministic.
    }
    // whole block outside the box -> skip the weight copy entirely
    int act = __syncthreads_count(!outb);
    if (act == 0) return;

    for (int i = threadIdx.x; i < CINC * HIDC; i += blockDim.x) sW[i] = g_cw[i];
    for (int i = threadIdx.x; i < HIDC; i += blockDim.x) sB[i] = g_cb[i];
    for (int i = threadIdx.x; i < 3 * HIDC; i += blockDim.x) sW2[i] = g_w2t[i];
    if (threadIdx.x < 3) sB2[threadIdx.x] = g_b2c[threadIdx.x];
    __syncthreads();
    if (outb) return;

    // ---- trilinear interp of 13 channels + analytic grad of channel 0 ----
    float ux = fminf(fmaxf((px + 1.0f) * 0.5f * 127.0f, 0.0f), 127.0f);
    float uy = fminf(fmaxf((py + 1.0f) * 0.5f * 127.0f, 0.0f), 127.0f);
    float uz = fminf(fmaxf((pz + 1.0f) * 0.5f * 127.0f, 0.0f), 127.0f);
    int ix = min((int)ux, RR - 2);
    int iy = min((int)uy, RR - 2);
    int iz = min((int)uz, RR - 2);
    float fx = ux - (float)ix, fy = uy - (float)iy, fz = uz - (float)iz;
    float wx[2] = {1.0f - fx, fx};
    float wy[2] = {1.0f - fy, fy};
    float wz[2] = {1.0f - fz, fz};

    const float* gp = grid + ((size_t)((ix * RR + iy) * RR + iz)) * GC;
    float vv[GC];
#pragma unroll
    for (int c = 0; c < GC; c++) vv[c] = 0.0f;
    float gxa = 0.0f, gya = 0.0f, gza = 0.0f;

#pragma unroll
    for (int cx = 0; cx < 2; cx++) {
#pragma unroll
        for (int cy = 0; cy < 2; cy++) {
#pragma unroll
            for (int cz = 0; cz < 2; cz++) {
                const float* cp = gp + cx * (RR * RR * GC) + cy * (RR * GC) + cz * GC;
                float wyz = wy[cy] * wz[cz];
                float wxz = wx[cx] * wz[cz];
                float wxy = wx[cx] * wy[cy];
                float w   = wx[cx] * wyz;
                float c0  = cp[0];
                vv[0] = fmaf(w, c0, vv[0]);
                gxa = fmaf(cx ? wyz : -wyz, c0, gxa);
                gya = fmaf(cy ? wxz : -wxz, c0, gya);
                gza = fmaf(cz ? wxy : -wxy, c0, gza);
#pragma unroll
                for (int c = 1; c < GC; c++) vv[c] = fmaf(w, cp[c], vv[c]);
            }
        }
    }

    // ---- assemble inputs: [pt, grad, viewdir, lat(folded)] ----
    float hh[CINC];
    hh[0] = px; hh[1] = py; hh[2] = pz;
    hh[3] = gxa * 63.5f; hh[4] = gya * 63.5f; hh[5] = gza * 63.5f;
    hh[6] = vdir[ray * 3 + 0]; hh[7] = vdir[ray * 3 + 1]; hh[8] = vdir[ray * 3 + 2];
#pragma unroll
    for (int l = 0; l < LATC; l++) hh[9 + l] = vv[1 + l];

    // ---- MLP: hidden = relu(h @ CW + cb); rgb = sigmoid(hidden @ W2 + b2) ----
    const float4* sW4  = (const float4*)sW;
    const float4* sB4  = (const float4*)sB;
    const float4* sW24 = (const float4*)sW2;
    float r0 = 0.0f, r1 = 0.0f, r2 = 0.0f;
    for (int jq = 0; jq < HIDC / 4; jq++) {
        float4 a = sB4[jq];
#pragma unroll
        for (int k = 0; k < CINC; k++) {
            float4 wv = sW4[k * (HIDC / 4) + jq];
            a.x = fmaf(hh[k], wv.x, a.x);
            a.y = fmaf(hh[k], wv.y, a.y);
            a.z = fmaf(hh[k], wv.z, a.z);
            a.w = fmaf(hh[k], wv.w, a.w);
        }
        a.x = fmaxf(a.x, 0.0f);
        a.y = fmaxf(a.y, 0.0f);
        a.z = fmaxf(a.z, 0.0f);
        a.w = fmaxf(a.w, 0.0f);
        float4 w0 = sW24[0 * (HIDC / 4) + jq];
        float4 w1 = sW24[1 * (HIDC / 4) + jq];
        float4 w2 = sW24[2 * (HIDC / 4) + jq];
        r0 = fmaf(a.x, w0.x, fmaf(a.y, w0.y, fmaf(a.z, w0.z, fmaf(a.w, w0.w, r0))));
        r1 = fmaf(a.x, w1.x, fmaf(a.y, w1.y, fmaf(a.z, w1.z, fmaf(a.w, w1.w, r1))));
        r2 = fmaf(a.x, w2.x, fmaf(a.y, w2.y, fmaf(a.z, w2.z, fmaf(a.w, w2.w, r2))));
    }
    g_sdf[idx] = vv[0];
    g_rgbp[idx * 3 + 0] = 1.0f / (1.0f + expf(-(r0 + sB2[0])));
    g_rgbp[idx * 3 + 1] = 1.0f / (1.0f + expf(-(r1 + sB2[1])));
    g_rgbp[idx * 3 + 2] = 1.0f / (1.0f + expf(-(r2 + sB2[2])));
}

// ---------------- per-ray: transmittance scan + accumulation ----------------
__global__ void __launch_bounds__(256)
integrate_kernel(const float* __restrict__ rd, const float* __restrict__ beta_p,
                 float* __restrict__ out) {
    int gwarp = (blockIdx.x * blockDim.x + threadIdx.x) >> 5;
    int lane  = threadIdx.x & 31;
    if (gwarp >= NB) return;
    const unsigned FULL = 0xffffffffu;

    float beff = fabsf(beta_p[0]) + 1e-4f;
    float rb   = 1.0f / beff;
    float dx = rd[gwarp * 3 + 0], dy = rd[gwarp * 3 + 1], dz = rd[gwarp * 3 + 2];
    float dn = sqrtf(dx * dx + dy * dy + dz * dz);

    float carry = 0.0f, aR = 0.0f, aG = 0.0f, aB = 0.0f, aD = 0.0f;

    for (int chunk = 0; chunk < (NS + 31) / 32; chunk++) {
        int s = chunk * 32 + lane;
        bool in = s < NS;
        float sdf = in ? g_sdf[gwarp * NS + s] : 100.0f;

        float lin = __fmul_rn((float)s, 1.0f / 499.0f);
        float z   = __fadd_rn(0.5f, __fmul_rn(3.0f, lin));
        int sd = (s >= NS - 1) ? NS - 2 : s;
        float l0 = __fmul_rn((float)sd, 1.0f / 499.0f);
        float l1 = __fmul_rn((float)(sd + 1), 1.0f / 499.0f);
        float z0 = __fadd_rn(0.5f, __fmul_rn(3.0f, l0));
        float z1 = __fadd_rn(0.5f, __fmul_rn(3.0f, l1));
        float dist = z1 - z0;

        float asdf = fabsf(sdf);
        float sgn  = (sdf > 0.0f) ? 1.0f : ((sdf < 0.0f) ? -1.0f : 0.0f);
        float density = rb * (0.5f + 0.5f * sgn * expm1f(-asdf / beff));
        float fe = in ? dist * density : 0.0f;

        // inclusive warp scan of fe
        float sc = fe;
#pragma unroll
        for (int o = 1; o < 32; o <<= 1) {
            float t = __shfl_up_sync(FULL, sc, o);
            if (lane >= o) sc += t;
        }
        float T     = expf(-(carry + (sc - fe)));   // exclusive prefix
        float alpha = 1.0f - expf(-fe);
        float w     = in ? alpha * T : 0.0f;

        if (in && w != 0.0f) {
            int bidx = (gwarp * NS + s) * 3;
            aR = fmaf(w, g_rgbp[bidx + 0], aR);
            aG = fmaf(w, g_rgbp[bidx + 1], aG);
            aB = fmaf(w, g_rgbp[bidx + 2], aB);
        }
        if (in) aD = fmaf(w, z * dn, aD);
        carry += __shfl_sync(FULL, sc, 31);
    }

#pragma unroll
    for (int o = 16; o > 0; o >>= 1) {
        aR += __shfl_down_sync(FULL, aR, o);
        aG += __shfl_down_sync(FULL, aG, o);
        aB += __shfl_down_sync(FULL, aB, o);
        aD += __shfl_down_sync(FULL, aD, o);
    }
    if (lane == 0) {
        out[gwarp * 3 + 0] = aR;
        out[gwarp * 3 + 1] = aG;
        out[gwarp * 3 + 2] = aB;
        out[3 * NB + gwarp] = aD;
    }
}

// ---------------- launch -----------------------------------------------------
extern "C" void kernel_launch(void* const* d_in, const int* in_sizes, int n_in,
                              void* d_out, int out_size) {
    const float* ro   = (const float*)d_in[0];
    const float* rd   = (const float*)d_in[1];
    const float* vd   = (const float*)d_in[2];
    const float* grid = (const float*)d_in[3];
    const float* Wf   = (const float*)d_in[4];
    const float* bf   = (const float*)d_in[5];
    const float* W1   = (const float*)d_in[6];
    const float* b1   = (const float*)d_in[7];
    const float* W2   = (const float*)d_in[8];
    const float* b2   = (const float*)d_in[9];
    const float* beta = (const float*)d_in[10];
    float* out = (float*)d_out;

    prep_kernel<<<LATC + 1, HIDC>>>(Wf, bf, W1, b1, W2, b2);
    point_kernel<<<(NB * NS) / 256, 256>>>(ro, rd, vd, grid);
    integrate_kernel<<<(NB * 32 + 255) / 256, 256>>>(rd, beta, out);
}